// round 2
// baseline (speedup 1.0000x reference)
#include <cuda_runtime.h>
#include <math.h>

#define Bn 8
#define Tn 512
#define Dn 1024
#define Rn 4
#define Vn 2048
#define Nn (Vn*Rn*Rn)   // 32768 columns of w_vocab

// ---------------- scratch (no allocations allowed) ----------------
__device__ float g_partial[8*Bn*Dn];   // [tchunk][b][d]
__device__ float g_xmean[Bn*Dn];       // [b][d]
__device__ float g_core[Bn*Nn];        // [b][n], n = i*(V*R) + y*R + j
__device__ float g_alpha[Bn*Rn];
__device__ float g_beta[Bn*Rn];
__device__ float g_lossb[Bn];

// ---------------- K1a: partial sums over T chunks ----------------
// grid (8 tchunks, 8 b), 256 threads; each thread owns 4 d's (float4)
__global__ void k_partial(const float* __restrict__ x) {
    int tc = blockIdx.x, b = blockIdx.y;
    int d4 = threadIdx.x * 4;
    const float* p = x + ((b * Tn) + tc * 64) * Dn + d4;
    float4 acc = make_float4(0.f, 0.f, 0.f, 0.f);
    #pragma unroll 8
    for (int t = 0; t < 64; t++) {
        float4 v = *(const float4*)(p + t * Dn);
        acc.x += v.x; acc.y += v.y; acc.z += v.z; acc.w += v.w;
    }
    *(float4*)&g_partial[(tc * Bn + b) * Dn + d4] = acc;
}

// ---------------- K1b: finalize mean ----------------
// grid 32, 256 threads; idx = b*1024 + d
__global__ void k_xmean() {
    int idx = blockIdx.x * 256 + threadIdx.x;
    float s = 0.f;
    #pragma unroll
    for (int tc = 0; tc < 8; tc++) s += g_partial[tc * (Bn*Dn) + idx];
    g_xmean[idx] = s * (1.0f / (float)Tn);
}

// ---------------- K2: core GEMM + alpha/beta ----------------
// blocks 0..127: core[b][n] = sum_d xmean[b][d] * wv[d][n]   (HBM-bound: 134 MB)
// block 128: alpha/beta (64 outputs, 4-thread split-K + shfl)
__global__ void k_gemm(const float* __restrict__ wv,
                       const float* __restrict__ wa,
                       const float* __restrict__ wb) {
    if (blockIdx.x < 128) {
        __shared__ float xs[Dn * Bn];   // xs[d*8 + b], broadcast reads in loop
        for (int i = threadIdx.x; i < Bn * Dn; i += 256) {
            int b = i >> 10, d = i & 1023;
            xs[d * 8 + b] = g_xmean[i];
        }
        __syncthreads();

        int n = blockIdx.x * 256 + threadIdx.x;
        float acc[8];
        #pragma unroll
        for (int b = 0; b < 8; b++) acc[b] = 0.f;

        const float* w = wv + n;
        #pragma unroll 8
        for (int d = 0; d < Dn; d++) {
            float wval = __ldg(&w[d * Nn]);
            float4 xa = *(const float4*)&xs[d * 8];
            float4 xb = *(const float4*)&xs[d * 8 + 4];
            acc[0] = fmaf(xa.x, wval, acc[0]);
            acc[1] = fmaf(xa.y, wval, acc[1]);
            acc[2] = fmaf(xa.z, wval, acc[2]);
            acc[3] = fmaf(xa.w, wval, acc[3]);
            acc[4] = fmaf(xb.x, wval, acc[4]);
            acc[5] = fmaf(xb.y, wval, acc[5]);
            acc[6] = fmaf(xb.z, wval, acc[6]);
            acc[7] = fmaf(xb.w, wval, acc[7]);
        }
        #pragma unroll
        for (int b = 0; b < 8; b++) g_core[b * Nn + n] = acc[b];
    } else {
        // alpha/beta: o = mat*32 + b*4 + r ; 4 threads per output
        int tid = threadIdx.x;
        int o = tid >> 2, l4 = tid & 3;
        int mat = o >> 5, b = (o >> 2) & 7, r = o & 3;
        const float* wm = mat ? wb : wa;
        float s = 0.f;
        int d0 = l4 * 256;
        #pragma unroll 4
        for (int d = d0; d < d0 + 256; d++)
            s = fmaf(g_xmean[b * Dn + d], wm[d * Rn + r], s);
        s += __shfl_down_sync(0xffffffffu, s, 2, 4);
        s += __shfl_down_sync(0xffffffffu, s, 1, 4);
        if (l4 == 0) {
            if (mat) g_beta[b * Rn + r] = s;
            else     g_alpha[b * Rn + r] = s;
        }
    }
}

// ---------------- K3: gather + normalize + tree product + loss ----------------
// grid 8 (one block per batch), 256 threads.
// Level 0 fused: each thread normalizes matrices for t=2k,2k+1 in registers and
// multiplies them immediately -> 256 matrices into smem. Then 8-level tree.
#define MST 17   // smem matrix stride (floats) to break bank conflicts

__global__ void k_tt(const int* __restrict__ labels) {
    __shared__ float bufA[256 * MST];  // 17408 B
    __shared__ float bufB[128 * MST];  //  8704 B
    int b = blockIdx.x;
    const float* cp = g_core + b * Nn;

    int k = threadIdx.x;          // pair index, t = 2k, 2k+1
    {
        float M0[16], M1[16];
        #pragma unroll
        for (int half = 0; half < 2; half++) {
            int t = 2 * k + half;
            int y = labels[b * Tn + t];
            float4 r0 = *(const float4*)(cp + 0 * (Vn*Rn) + y * 4);
            float4 r1 = *(const float4*)(cp + 1 * (Vn*Rn) + y * 4);
            float4 r2 = *(const float4*)(cp + 2 * (Vn*Rn) + y * 4);
            float4 r3 = *(const float4*)(cp + 3 * (Vn*Rn) + y * 4);
            r0.x = fabsf(r0.x); r0.y = fabsf(r0.y); r0.z = fabsf(r0.z); r0.w = fabsf(r0.w);
            r1.x = fabsf(r1.x); r1.y = fabsf(r1.y); r1.z = fabsf(r1.z); r1.w = fabsf(r1.w);
            r2.x = fabsf(r2.x); r2.y = fabsf(r2.y); r2.z = fabsf(r2.z); r2.w = fabsf(r2.w);
            r3.x = fabsf(r3.x); r3.y = fabsf(r3.y); r3.z = fabsf(r3.z); r3.w = fabsf(r3.w);
            // column sums (normalize over i, i.e. axis=2 in reference)
            float4 s = make_float4(r0.x + r1.x + r2.x + r3.x,
                                   r0.y + r1.y + r2.y + r3.y,
                                   r0.z + r1.z + r2.z + r3.z,
                                   r0.w + r1.w + r2.w + r3.w);
            float4 inv = make_float4(1.0f / s.x, 1.0f / s.y, 1.0f / s.z, 1.0f / s.w);
            float* M = half ? M1 : M0;
            M[ 0] = r0.x * inv.x; M[ 1] = r0.y * inv.y; M[ 2] = r0.z * inv.z; M[ 3] = r0.w * inv.w;
            M[ 4] = r1.x * inv.x; M[ 5] = r1.y * inv.y; M[ 6] = r1.z * inv.z; M[ 7] = r1.w * inv.w;
            M[ 8] = r2.x * inv.x; M[ 9] = r2.y * inv.y; M[10] = r2.z * inv.z; M[11] = r2.w * inv.w;
            M[12] = r3.x * inv.x; M[13] = r3.y * inv.y; M[14] = r3.z * inv.z; M[15] = r3.w * inv.w;
        }
        // C = M1 @ M0  (later matrix applied on the left)
        float* dstM = bufA + k * MST;
        #pragma unroll
        for (int i = 0; i < 4; i++) {
            float c0 = 0.f, c1 = 0.f, c2 = 0.f, c3 = 0.f;
            #pragma unroll
            for (int l = 0; l < 4; l++) {
                float a = M1[i * 4 + l];
                c0 = fmaf(a, M0[l * 4 + 0], c0);
                c1 = fmaf(a, M0[l * 4 + 1], c1);
                c2 = fmaf(a, M0[l * 4 + 2], c2);
                c3 = fmaf(a, M0[l * 4 + 3], c3);
            }
            dstM[i * 4 + 0] = c0; dstM[i * 4 + 1] = c1;
            dstM[i * 4 + 2] = c2; dstM[i * 4 + 3] = c3;
        }
    }
    __syncthreads();

    // tree: 256 -> 128 -> ... -> 1 (ping-pong bufA/bufB)
    float* src = bufA;
    float* dst = bufB;
    for (int nmat = 128; nmat >= 1; nmat >>= 1) {
        for (int kk = threadIdx.x; kk < nmat; kk += 256) {
            const float* A0 = src + (2 * kk) * MST;       // earlier product
            const float* A1 = src + (2 * kk + 1) * MST;   // later product
            float* C = dst + kk * MST;
            #pragma unroll
            for (int i = 0; i < 4; i++) {
                float c0 = 0.f, c1 = 0.f, c2 = 0.f, c3 = 0.f;
                #pragma unroll
                for (int l = 0; l < 4; l++) {
                    float a = A1[i * 4 + l];
                    c0 = fmaf(a, A0[l * 4 + 0], c0);
                    c1 = fmaf(a, A0[l * 4 + 1], c1);
                    c2 = fmaf(a, A0[l * 4 + 2], c2);
                    c3 = fmaf(a, A0[l * 4 + 3], c3);
                }
                C[i * 4 + 0] = c0; C[i * 4 + 1] = c1;
                C[i * 4 + 2] = c2; C[i * 4 + 3] = c3;
            }
        }
        __syncthreads();
        float* tmp = src; src = dst; dst = tmp;
    }
    // final product now at src[0..15]

    if (threadIdx.x == 0) {
        const float* P = src;
        float a0 = fabsf(g_alpha[b * 4 + 0]);
        float a1 = fabsf(g_alpha[b * 4 + 1]);
        float a2 = fabsf(g_alpha[b * 4 + 2]);
        float a3 = fabsf(g_alpha[b * 4 + 3]);
        float sa = a0 + a1 + a2 + a3;
        float v0 = a0 / sa, v1 = a1 / sa, v2 = a2 / sa, v3 = a3 / sa;
        float w0 = P[ 0]*v0 + P[ 1]*v1 + P[ 2]*v2 + P[ 3]*v3;
        float w1 = P[ 4]*v0 + P[ 5]*v1 + P[ 6]*v2 + P[ 7]*v3;
        float w2 = P[ 8]*v0 + P[ 9]*v1 + P[10]*v2 + P[11]*v3;
        float w3 = P[12]*v0 + P[13]*v1 + P[14]*v2 + P[15]*v3;
        float b0 = fabsf(g_beta[b * 4 + 0]);
        float b1 = fabsf(g_beta[b * 4 + 1]);
        float b2 = fabsf(g_beta[b * 4 + 2]);
        float b3 = fabsf(g_beta[b * 4 + 3]);
        float sb = b0 + b1 + b2 + b3;
        float prob = (b0 * w0 + b1 * w1 + b2 * w2 + b3 * w3) / sb;
        g_lossb[b] = -logf(prob);
    }
}

// ---------------- K4: final mean over batches ----------------
__global__ void k_final(float* __restrict__ out) {
    float s = 0.f;
    #pragma unroll
    for (int b = 0; b < Bn; b++) s += g_lossb[b];
    out[0] = s * (1.0f / (float)Bn);
}

// ---------------- launch ----------------
extern "C" void kernel_launch(void* const* d_in, const int* in_sizes, int n_in,
                              void* d_out, int out_size) {
    const float* x      = (const float*)d_in[0];  // [B,T,D] f32
    const int*   labels = (const int*)  d_in[1];  // [B,T] i32
    const float* wa     = (const float*)d_in[2];  // [D,R]
    const float* wb     = (const float*)d_in[3];  // [D,R]
    const float* wv     = (const float*)d_in[4];  // [D,V*R*R]

    k_partial<<<dim3(8, Bn), 256>>>(x);
    k_xmean<<<32, 256>>>();
    k_gemm<<<129, 256>>>(wv, wa, wb);
    k_tt<<<Bn, 256>>>(labels);
    k_final<<<1, 1>>>((float*)d_out);
}

// round 3
// speedup vs baseline: 2.2086x; 2.2086x over previous
#include <cuda_runtime.h>
#include <math.h>

#define Bn 8
#define Tn 512
#define Dn 1024
#define Rn 4
#define Vn 2048
#define Nn (Vn*Rn*Rn)   // 32768 columns of w_vocab
#define TC 32            // t-chunks in stage-1 reduction
#define KS 4             // split-K factor for core GEMM
#define DKS (Dn/KS)      // 256 d-rows per split

// ---------------- scratch (no allocations allowed) ----------------
__device__ float g_partial[TC*Bn*Dn];     // [tchunk][b][d]  (1 MB)
__device__ float g_xmean[Bn*Dn];          // [b][d]
__device__ float g_corep[KS*Bn*Nn];       // split-K partials (4 MB)
__device__ float g_core[Bn*Nn];           // [b][n], n = i*(V*R) + y*R + j
__device__ float g_alpha[Bn*Rn];
__device__ float g_beta[Bn*Rn];
__device__ float g_lossb[Bn];

// ---------------- K1a: partial sums over T chunks ----------------
// grid (TC, 8), 256 threads; each thread owns 4 d's (float4), 16 t-rows
__global__ void k_partial(const float* __restrict__ x) {
    int tc = blockIdx.x, b = blockIdx.y;
    int d4 = threadIdx.x * 4;
    const float* p = x + ((size_t)(b * Tn) + tc * (Tn/TC)) * Dn + d4;
    float4 acc = make_float4(0.f, 0.f, 0.f, 0.f);
    #pragma unroll
    for (int t = 0; t < Tn/TC; t++) {
        float4 v = *(const float4*)(p + (size_t)t * Dn);
        acc.x += v.x; acc.y += v.y; acc.z += v.z; acc.w += v.w;
    }
    *(float4*)&g_partial[(tc * Bn + b) * Dn + d4] = acc;
}

// ---------------- K1b: finalize mean ----------------
// grid 32, 256 threads; idx = b*1024 + d
__global__ void k_xmean() {
    int idx = blockIdx.x * 256 + threadIdx.x;
    float s = 0.f;
    #pragma unroll
    for (int tc = 0; tc < TC; tc++) s += g_partial[tc * (Bn*Dn) + idx];
    g_xmean[idx] = s * (1.0f / (float)Tn);
}

// ---------------- K2: split-K core GEMM ----------------
// grid (128 n-tiles, KS), 256 threads. Each thread: one n column, 256 d-rows,
// 16-deep independent LDG batches for MLP. corep[ks][b][n] partials.
__global__ void __launch_bounds__(256) k_gemm(const float* __restrict__ wv) {
    __shared__ float xs[DKS * Bn];   // xs[dd*8 + b]
    int ks = blockIdx.y;
    int d0 = ks * DKS;
    for (int i = threadIdx.x; i < Bn * DKS; i += 256) {
        int b = i >> 8, dd = i & (DKS-1);
        xs[dd * 8 + b] = g_xmean[b * Dn + d0 + dd];
    }
    __syncthreads();

    int n = blockIdx.x * 256 + threadIdx.x;
    float acc[8];
    #pragma unroll
    for (int b = 0; b < 8; b++) acc[b] = 0.f;

    const float* w = wv + (size_t)d0 * Nn + n;
    #pragma unroll 1
    for (int du = 0; du < DKS; du += 16) {
        float wr[16];
        #pragma unroll
        for (int u = 0; u < 16; u++)
            wr[u] = __ldg(&w[(du + u) * Nn]);
        #pragma unroll
        for (int u = 0; u < 16; u++) {
            float4 xa = *(const float4*)&xs[(du + u) * 8];
            float4 xb = *(const float4*)&xs[(du + u) * 8 + 4];
            acc[0] = fmaf(xa.x, wr[u], acc[0]);
            acc[1] = fmaf(xa.y, wr[u], acc[1]);
            acc[2] = fmaf(xa.z, wr[u], acc[2]);
            acc[3] = fmaf(xa.w, wr[u], acc[3]);
            acc[4] = fmaf(xb.x, wr[u], acc[4]);
            acc[5] = fmaf(xb.y, wr[u], acc[5]);
            acc[6] = fmaf(xb.z, wr[u], acc[6]);
            acc[7] = fmaf(xb.w, wr[u], acc[7]);
        }
    }
    float* o = g_corep + (size_t)ks * (Bn*Nn) + n;
    #pragma unroll
    for (int b = 0; b < 8; b++) o[b * Nn] = acc[b];
}

// ---------------- K3: reduce split-K partials + alpha/beta ----------------
// blocks 0..255: float4 reduce of Bn*Nn elements. block 256: alpha/beta.
__global__ void k_reduce(const float* __restrict__ wa,
                         const float* __restrict__ wb) {
    if (blockIdx.x < 256) {
        int i4 = (blockIdx.x * 256 + threadIdx.x) * 4;
        float4 s = *(const float4*)&g_corep[i4];
        #pragma unroll
        for (int ks = 1; ks < KS; ks++) {
            float4 v = *(const float4*)&g_corep[ks * (Bn*Nn) + i4];
            s.x += v.x; s.y += v.y; s.z += v.z; s.w += v.w;
        }
        *(float4*)&g_core[i4] = s;
    } else {
        // alpha/beta: o = mat*32 + b*4 + r ; 4 threads per output
        int tid = threadIdx.x;
        int o = tid >> 2, l4 = tid & 3;
        int mat = o >> 5, b = (o >> 2) & 7, r = o & 3;
        const float* wm = mat ? wb : wa;
        float s = 0.f;
        int dd0 = l4 * 256;
        #pragma unroll 4
        for (int d = dd0; d < dd0 + 256; d++)
            s = fmaf(g_xmean[b * Dn + d], wm[d * Rn + r], s);
        s += __shfl_down_sync(0xffffffffu, s, 2, 4);
        s += __shfl_down_sync(0xffffffffu, s, 1, 4);
        if (l4 == 0) {
            if (mat) g_beta[b * Rn + r] = s;
            else     g_alpha[b * Rn + r] = s;
        }
    }
}

// ---------------- K4: gather + normalize + tree product + loss ----------------
#define MST 17   // smem matrix stride (floats) to break bank conflicts

__global__ void k_tt(const int* __restrict__ labels) {
    __shared__ float bufA[256 * MST];
    __shared__ float bufB[128 * MST];
    int b = blockIdx.x;
    const float* cp = g_core + b * Nn;

    int k = threadIdx.x;          // pair index, t = 2k, 2k+1
    {
        float M0[16], M1[16];
        #pragma unroll
        for (int half = 0; half < 2; half++) {
            int t = 2 * k + half;
            int y = labels[b * Tn + t];
            float4 r0 = *(const float4*)(cp + 0 * (Vn*Rn) + y * 4);
            float4 r1 = *(const float4*)(cp + 1 * (Vn*Rn) + y * 4);
            float4 r2 = *(const float4*)(cp + 2 * (Vn*Rn) + y * 4);
            float4 r3 = *(const float4*)(cp + 3 * (Vn*Rn) + y * 4);
            r0.x = fabsf(r0.x); r0.y = fabsf(r0.y); r0.z = fabsf(r0.z); r0.w = fabsf(r0.w);
            r1.x = fabsf(r1.x); r1.y = fabsf(r1.y); r1.z = fabsf(r1.z); r1.w = fabsf(r1.w);
            r2.x = fabsf(r2.x); r2.y = fabsf(r2.y); r2.z = fabsf(r2.z); r2.w = fabsf(r2.w);
            r3.x = fabsf(r3.x); r3.y = fabsf(r3.y); r3.z = fabsf(r3.z); r3.w = fabsf(r3.w);
            float4 s = make_float4(r0.x + r1.x + r2.x + r3.x,
                                   r0.y + r1.y + r2.y + r3.y,
                                   r0.z + r1.z + r2.z + r3.z,
                                   r0.w + r1.w + r2.w + r3.w);
            float4 inv = make_float4(1.0f / s.x, 1.0f / s.y, 1.0f / s.z, 1.0f / s.w);
            float* M = half ? M1 : M0;
            M[ 0] = r0.x * inv.x; M[ 1] = r0.y * inv.y; M[ 2] = r0.z * inv.z; M[ 3] = r0.w * inv.w;
            M[ 4] = r1.x * inv.x; M[ 5] = r1.y * inv.y; M[ 6] = r1.z * inv.z; M[ 7] = r1.w * inv.w;
            M[ 8] = r2.x * inv.x; M[ 9] = r2.y * inv.y; M[10] = r2.z * inv.z; M[11] = r2.w * inv.w;
            M[12] = r3.x * inv.x; M[13] = r3.y * inv.y; M[14] = r3.z * inv.z; M[15] = r3.w * inv.w;
        }
        // C = M1 @ M0
        float* dstM = bufA + k * MST;
        #pragma unroll
        for (int i = 0; i < 4; i++) {
            float c0 = 0.f, c1 = 0.f, c2 = 0.f, c3 = 0.f;
            #pragma unroll
            for (int l = 0; l < 4; l++) {
                float a = M1[i * 4 + l];
                c0 = fmaf(a, M0[l * 4 + 0], c0);
                c1 = fmaf(a, M0[l * 4 + 1], c1);
                c2 = fmaf(a, M0[l * 4 + 2], c2);
                c3 = fmaf(a, M0[l * 4 + 3], c3);
            }
            dstM[i * 4 + 0] = c0; dstM[i * 4 + 1] = c1;
            dstM[i * 4 + 2] = c2; dstM[i * 4 + 3] = c3;
        }
    }
    __syncthreads();

    float* src = bufA;
    float* dst = bufB;
    for (int nmat = 128; nmat >= 1; nmat >>= 1) {
        for (int kk = threadIdx.x; kk < nmat; kk += 256) {
            const float* A0 = src + (2 * kk) * MST;
            const float* A1 = src + (2 * kk + 1) * MST;
            float* C = dst + kk * MST;
            #pragma unroll
            for (int i = 0; i < 4; i++) {
                float c0 = 0.f, c1 = 0.f, c2 = 0.f, c3 = 0.f;
                #pragma unroll
                for (int l = 0; l < 4; l++) {
                    float a = A1[i * 4 + l];
                    c0 = fmaf(a, A0[l * 4 + 0], c0);
                    c1 = fmaf(a, A0[l * 4 + 1], c1);
                    c2 = fmaf(a, A0[l * 4 + 2], c2);
                    c3 = fmaf(a, A0[l * 4 + 3], c3);
                }
                C[i * 4 + 0] = c0; C[i * 4 + 1] = c1;
                C[i * 4 + 2] = c2; C[i * 4 + 3] = c3;
            }
        }
        __syncthreads();
        float* tmp = src; src = dst; dst = tmp;
    }

    if (threadIdx.x == 0) {
        const float* P = src;
        float a0 = fabsf(g_alpha[b * 4 + 0]);
        float a1 = fabsf(g_alpha[b * 4 + 1]);
        float a2 = fabsf(g_alpha[b * 4 + 2]);
        float a3 = fabsf(g_alpha[b * 4 + 3]);
        float sa = a0 + a1 + a2 + a3;
        float v0 = a0 / sa, v1 = a1 / sa, v2 = a2 / sa, v3 = a3 / sa;
        float w0 = P[ 0]*v0 + P[ 1]*v1 + P[ 2]*v2 + P[ 3]*v3;
        float w1 = P[ 4]*v0 + P[ 5]*v1 + P[ 6]*v2 + P[ 7]*v3;
        float w2 = P[ 8]*v0 + P[ 9]*v1 + P[10]*v2 + P[11]*v3;
        float w3 = P[12]*v0 + P[13]*v1 + P[14]*v2 + P[15]*v3;
        float b0 = fabsf(g_beta[b * 4 + 0]);
        float b1 = fabsf(g_beta[b * 4 + 1]);
        float b2 = fabsf(g_beta[b * 4 + 2]);
        float b3 = fabsf(g_beta[b * 4 + 3]);
        float sb = b0 + b1 + b2 + b3;
        float prob = (b0 * w0 + b1 * w1 + b2 * w2 + b3 * w3) / sb;
        g_lossb[b] = -logf(prob);
    }
}

// ---------------- K5: final mean over batches ----------------
__global__ void k_final(float* __restrict__ out) {
    float s = 0.f;
    #pragma unroll
    for (int b = 0; b < Bn; b++) s += g_lossb[b];
    out[0] = s * (1.0f / (float)Bn);
}

// ---------------- launch ----------------
extern "C" void kernel_launch(void* const* d_in, const int* in_sizes, int n_in,
                              void* d_out, int out_size) {
    const float* x      = (const float*)d_in[0];  // [B,T,D] f32
    const int*   labels = (const int*)  d_in[1];  // [B,T] i32
    const float* wa     = (const float*)d_in[2];  // [D,R]
    const float* wb     = (const float*)d_in[3];  // [D,R]
    const float* wv     = (const float*)d_in[4];  // [D,V*R*R]

    k_partial<<<dim3(TC, Bn), 256>>>(x);
    k_xmean<<<32, 256>>>();
    k_gemm<<<dim3(128, KS), 256>>>(wv);
    k_reduce<<<257, 256>>>(wa, wb);
    k_tt<<<Bn, 256>>>(labels);
    k_final<<<1, 1>>>((float*)d_out);
}

// round 5
// speedup vs baseline: 2.9994x; 1.3581x over previous
#include <cuda_runtime.h>
#include <math.h>

#define Bn 8
#define Tn 512
#define Dn 1024
#define Rn 4
#define Vn 2048
#define Nn (Vn*Rn*Rn)   // 32768 columns of w_vocab
#define TC 32            // t-chunks in stage-1 reduction
#define KS 4             // split-K factor for core GEMM
#define DKS (Dn/KS)      // 256 d-rows per split

// ---------------- scratch (no allocations allowed) ----------------
__device__ float g_partial[TC*Bn*Dn];     // [tchunk][b][d]  (1 MB)
__device__ float g_xmean[Bn*Dn];          // [b][d]
__device__ float g_corep[KS*Bn*Nn];       // split-K partials (4 MB)
__device__ float g_alpha[Bn*Rn];
__device__ float g_beta[Bn*Rn];
__device__ float g_lossb[Bn];

// ---------------- K1a: partial sums over T chunks ----------------
__global__ void k_partial(const float* __restrict__ x) {
    int tc = blockIdx.x, b = blockIdx.y;
    int d4 = threadIdx.x * 4;
    const float* p = x + ((size_t)(b * Tn) + tc * (Tn/TC)) * Dn + d4;
    float4 acc = make_float4(0.f, 0.f, 0.f, 0.f);
    #pragma unroll
    for (int t = 0; t < Tn/TC; t++) {
        float4 v = *(const float4*)(p + (size_t)t * Dn);
        acc.x += v.x; acc.y += v.y; acc.z += v.z; acc.w += v.w;
    }
    *(float4*)&g_partial[(tc * Bn + b) * Dn + d4] = acc;
}

// ---------------- K1b: finalize mean ----------------
__global__ void k_xmean() {
    int idx = blockIdx.x * 256 + threadIdx.x;
    float s = 0.f;
    #pragma unroll
    for (int tc = 0; tc < TC; tc++) s += g_partial[tc * (Bn*Dn) + idx];
    g_xmean[idx] = s * (1.0f / (float)Tn);
}

// ---------------- K1c: alpha/beta, fully parallel ----------------
// grid 2 (mat), 1024 threads: 32 outputs x 32 lanes; lane sums 32 d's.
__global__ void __launch_bounds__(1024) k_ab(const float* __restrict__ wa,
                                             const float* __restrict__ wb) {
    int mat = blockIdx.x;
    int wid = threadIdx.x >> 5;       // output index 0..31
    int lane = threadIdx.x & 31;
    int b = wid >> 2, r = wid & 3;
    const float* wm = mat ? wb : wa;
    const float* xb = g_xmean + b * Dn;
    float s = 0.f;
    #pragma unroll
    for (int j = 0; j < 32; j++) {
        int d = lane + j * 32;
        s = fmaf(xb[d], __ldg(&wm[d * Rn + r]), s);
    }
    #pragma unroll
    for (int off = 16; off >= 1; off >>= 1)
        s += __shfl_down_sync(0xffffffffu, s, off);
    if (lane == 0) {
        if (mat) g_beta[b * Rn + r] = s;
        else     g_alpha[b * Rn + r] = s;
    }
}

// ---------------- K2: split-K core GEMM ----------------
__global__ void __launch_bounds__(256) k_gemm(const float* __restrict__ wv) {
    __shared__ float xs[DKS * Bn];   // xs[dd*8 + b]
    int ks = blockIdx.y;
    int d0 = ks * DKS;
    for (int i = threadIdx.x; i < Bn * DKS; i += 256) {
        int b = i >> 8, dd = i & (DKS-1);
        xs[dd * 8 + b] = g_xmean[b * Dn + d0 + dd];
    }
    __syncthreads();

    int n = blockIdx.x * 256 + threadIdx.x;
    float acc[8];
    #pragma unroll
    for (int b = 0; b < 8; b++) acc[b] = 0.f;

    const float* w = wv + (size_t)d0 * Nn + n;
    #pragma unroll 1
    for (int du = 0; du < DKS; du += 16) {
        float wr[16];
        #pragma unroll
        for (int u = 0; u < 16; u++)
            wr[u] = __ldg(&w[(du + u) * Nn]);
        #pragma unroll
        for (int u = 0; u < 16; u++) {
            float4 xa = *(const float4*)&xs[(du + u) * 8];
            float4 xb = *(const float4*)&xs[(du + u) * 8 + 4];
            acc[0] = fmaf(xa.x, wr[u], acc[0]);
            acc[1] = fmaf(xa.y, wr[u], acc[1]);
            acc[2] = fmaf(xa.z, wr[u], acc[2]);
            acc[3] = fmaf(xa.w, wr[u], acc[3]);
            acc[4] = fmaf(xb.x, wr[u], acc[4]);
            acc[5] = fmaf(xb.y, wr[u], acc[5]);
            acc[6] = fmaf(xb.z, wr[u], acc[6]);
            acc[7] = fmaf(xb.w, wr[u], acc[7]);
        }
    }
    float* o = g_corep + (size_t)ks * (Bn*Nn) + n;
    #pragma unroll
    for (int b = 0; b < 8; b++) o[b * Nn] = acc[b];
}

// ---------------- K3: gather(+splitK sum) + normalize + tree + loss ----------------
#define MST 17   // smem matrix stride to break bank conflicts

__global__ void k_tt(const int* __restrict__ labels) {
    __shared__ float bufA[256 * MST];
    __shared__ float bufB[128 * MST];
    int b = blockIdx.x;
    const float* cp = g_corep + (size_t)b * Nn;

    int k = threadIdx.x;          // pair index, t = 2k, 2k+1
    {
        // load both labels first (one DRAM latency chain)
        int y0 = __ldg(&labels[b * Tn + 2 * k]);
        int y1 = __ldg(&labels[b * Tn + 2 * k + 1]);

        // gather rows for both halves, summing KS partials (all LDGs independent)
        float4 rows[2][4];
        #pragma unroll
        for (int half = 0; half < 2; half++) {
            int y = half ? y1 : y0;
            #pragma unroll
            for (int i = 0; i < 4; i++) {
                const float* base = cp + i * (Vn*Rn) + y * 4;
                float4 s = __ldg((const float4*)base);
                #pragma unroll
                for (int ks = 1; ks < KS; ks++) {
                    float4 v = __ldg((const float4*)(base + (size_t)ks * (Bn*Nn)));
                    s.x += v.x; s.y += v.y; s.z += v.z; s.w += v.w;
                }
                rows[half][i] = s;
            }
        }

        float M0[16], M1[16];
        #pragma unroll
        for (int half = 0; half < 2; half++) {
            float4 r0 = rows[half][0], r1 = rows[half][1];
            float4 r2 = rows[half][2], r3 = rows[half][3];
            r0.x = fabsf(r0.x); r0.y = fabsf(r0.y); r0.z = fabsf(r0.z); r0.w = fabsf(r0.w);
            r1.x = fabsf(r1.x); r1.y = fabsf(r1.y); r1.z = fabsf(r1.z); r1.w = fabsf(r1.w);
            r2.x = fabsf(r2.x); r2.y = fabsf(r2.y); r2.z = fabsf(r2.z); r2.w = fabsf(r2.w);
            r3.x = fabsf(r3.x); r3.y = fabsf(r3.y); r3.z = fabsf(r3.z); r3.w = fabsf(r3.w);
            float4 s = make_float4(r0.x + r1.x + r2.x + r3.x,
                                   r0.y + r1.y + r2.y + r3.y,
                                   r0.z + r1.z + r2.z + r3.z,
                                   r0.w + r1.w + r2.w + r3.w);
            float4 inv = make_float4(1.0f / s.x, 1.0f / s.y, 1.0f / s.z, 1.0f / s.w);
            float* M = half ? M1 : M0;
            M[ 0] = r0.x * inv.x; M[ 1] = r0.y * inv.y; M[ 2] = r0.z * inv.z; M[ 3] = r0.w * inv.w;
            M[ 4] = r1.x * inv.x; M[ 5] = r1.y * inv.y; M[ 6] = r1.z * inv.z; M[ 7] = r1.w * inv.w;
            M[ 8] = r2.x * inv.x; M[ 9] = r2.y * inv.y; M[10] = r2.z * inv.z; M[11] = r2.w * inv.w;
            M[12] = r3.x * inv.x; M[13] = r3.y * inv.y; M[14] = r3.z * inv.z; M[15] = r3.w * inv.w;
        }
        // C = M1 @ M0
        float* dstM = bufA + k * MST;
        #pragma unroll
        for (int i = 0; i < 4; i++) {
            float c0 = 0.f, c1 = 0.f, c2 = 0.f, c3 = 0.f;
            #pragma unroll
            for (int l = 0; l < 4; l++) {
                float a = M1[i * 4 + l];
                c0 = fmaf(a, M0[l * 4 + 0], c0);
                c1 = fmaf(a, M0[l * 4 + 1], c1);
                c2 = fmaf(a, M0[l * 4 + 2], c2);
                c3 = fmaf(a, M0[l * 4 + 3], c3);
            }
            dstM[i * 4 + 0] = c0; dstM[i * 4 + 1] = c1;
            dstM[i * 4 + 2] = c2; dstM[i * 4 + 3] = c3;
        }
    }
    __syncthreads();

    float* src = bufA;
    float* dst = bufB;
    for (int nmat = 128; nmat >= 1; nmat >>= 1) {
        for (int kk = threadIdx.x; kk < nmat; kk += 256) {
            const float* A0 = src + (2 * kk) * MST;
            const float* A1 = src + (2 * kk + 1) * MST;
            float* C = dst + kk * MST;
            #pragma unroll
            for (int i = 0; i < 4; i++) {
                float c0 = 0.f, c1 = 0.f, c2 = 0.f, c3 = 0.f;
                #pragma unroll
                for (int l = 0; l < 4; l++) {
                    float a = A1[i * 4 + l];
                    c0 = fmaf(a, A0[l * 4 + 0], c0);
                    c1 = fmaf(a, A0[l * 4 + 1], c1);
                    c2 = fmaf(a, A0[l * 4 + 2], c2);
                    c3 = fmaf(a, A0[l * 4 + 3], c3);
                }
                C[i * 4 + 0] = c0; C[i * 4 + 1] = c1;
                C[i * 4 + 2] = c2; C[i * 4 + 3] = c3;
            }
        }
        __syncthreads();
        float* tmp = src; src = dst; dst = tmp;
    }

    if (threadIdx.x == 0) {
        const float* P = src;
        float a0 = fabsf(g_alpha[b * 4 + 0]);
        float a1 = fabsf(g_alpha[b * 4 + 1]);
        float a2 = fabsf(g_alpha[b * 4 + 2]);
        float a3 = fabsf(g_alpha[b * 4 + 3]);
        float sa = a0 + a1 + a2 + a3;
        float v0 = a0 / sa, v1 = a1 / sa, v2 = a2 / sa, v3 = a3 / sa;
        float w0 = P[ 0]*v0 + P[ 1]*v1 + P[ 2]*v2 + P[ 3]*v3;
        float w1 = P[ 4]*v0 + P[ 5]*v1 + P[ 6]*v2 + P[ 7]*v3;
        float w2 = P[ 8]*v0 + P[ 9]*v1 + P[10]*v2 + P[11]*v3;
        float w3 = P[12]*v0 + P[13]*v1 + P[14]*v2 + P[15]*v3;
        float b0 = fabsf(g_beta[b * 4 + 0]);
        float b1 = fabsf(g_beta[b * 4 + 1]);
        float b2 = fabsf(g_beta[b * 4 + 2]);
        float b3 = fabsf(g_beta[b * 4 + 3]);
        float sb = b0 + b1 + b2 + b3;
        float prob = (b0 * w0 + b1 * w1 + b2 * w2 + b3 * w3) / sb;
        g_lossb[b] = -logf(prob);
    }
}

// ---------------- K5: final mean over batches ----------------
__global__ void k_final(float* __restrict__ out) {
    float s = 0.f;
    #pragma unroll
    for (int b = 0; b < Bn; b++) s += g_lossb[b];
    out[0] = s * (1.0f / (float)Bn);
}

// ---------------- launch ----------------
extern "C" void kernel_launch(void* const* d_in, const int* in_sizes, int n_in,
                              void* d_out, int out_size) {
    const float* x      = (const float*)d_in[0];  // [B,T,D] f32
    const int*   labels = (const int*)  d_in[1];  // [B,T] i32
    const float* wa     = (const float*)d_in[2];  // [D,R]
    const float* wb     = (const float*)d_in[3];  // [D,R]
    const float* wv     = (const float*)d_in[4];  // [D,V*R*R]

    k_partial<<<dim3(TC, Bn), 256>>>(x);
    k_xmean<<<32, 256>>>();
    k_ab<<<2, 1024>>>(wa, wb);
    k_gemm<<<dim3(128, KS), 256>>>(wv);
    k_tt<<<Bn, 256>>>(labels);
    k_final<<<1, 1>>>((float*)d_out);
}